// round 5
// baseline (speedup 1.0000x reference)
#include <cuda_runtime.h>

#define N_POINTS 300000
#define N_PAIRS  100000
#define K_OFFSETS 27
#define C_IN 32
#define C_OUT 64
#define GROUPS 8
#define EPS_GN 1e-5f
#define NEG_SLOPE 0.01f

// ---------------- device scratch (no allocations allowed) ----------------
__device__ float g_sum[GROUPS];
__device__ float g_sqs[GROUPS];
__device__ __align__(16) float g_scale[C_OUT];
__device__ __align__(16) float g_bias[C_OUT];

// ---------------- f32x2 packed-math helpers (Blackwell FFMA2) ------------
__device__ __forceinline__ unsigned long long pk2(float lo, float hi) {
    unsigned long long r;
    asm("mov.b64 %0, {%1, %2};" : "=l"(r) : "f"(lo), "f"(hi));
    return r;
}
__device__ __forceinline__ void unpk2(unsigned long long v, float& lo, float& hi) {
    asm("mov.b64 {%0, %1}, %2;" : "=f"(lo), "=f"(hi) : "l"(v));
}
__device__ __forceinline__ unsigned long long fma2(unsigned long long a,
                                                   unsigned long long b,
                                                   unsigned long long c) {
    unsigned long long d;
    asm("fma.rn.f32x2 %0, %1, %2, %3;" : "=l"(d) : "l"(a), "l"(b), "l"(c));
    return d;
}

// ---------------- K0: zero output + zero stat scratch --------------------
__global__ void zero_kernel(float4* __restrict__ out) {
    const int total4 = N_POINTS * C_OUT / 4;
    int i = blockIdx.x * blockDim.x + threadIdx.x;
    if (i < total4) out[i] = make_float4(0.f, 0.f, 0.f, 0.f);
    if (blockIdx.x == 0 && threadIdx.x < GROUPS) {
        g_sum[threadIdx.x] = 0.f;
        g_sqs[threadIdx.x] = 0.f;
    }
}

// ---------------- K1: gather -> 32x64 matmul -> vector scatter-add -------
// One warp per pair. Lane = hi*16 + q:
//   hi in {0,1}  -> which half of the 32 input channels this lane reduces
//   q  in 0..15  -> this lane owns output channels [4q, 4q+4)
// Weights for (k, i in hi-half, 4 channels) live in registers as f32x2 pairs.
__global__ void __launch_bounds__(256, 2)
conv_kernel(const float* __restrict__ feats,
            const float* __restrict__ weight,
            const int* __restrict__ in_idx,
            const int* __restrict__ out_idx,
            float* __restrict__ out) {
    const int k    = blockIdx.y;
    const int lane = threadIdx.x & 31;
    const int warp = threadIdx.x >> 5;
    const int hi   = lane >> 4;
    const int q    = lane & 15;
    const int c0   = q << 2;

    // Load this lane's weight slice: i = hi*16 + j, channels c0..c0+3
    unsigned long long w0[16], w1[16];
    const float* wk = weight + (size_t)k * (C_IN * C_OUT);
    #pragma unroll
    for (int j = 0; j < 16; ++j) {
        float4 v = *(const float4*)(wk + (size_t)(hi * 16 + j) * C_OUT + c0);
        w0[j] = pk2(v.x, v.y);
        w1[j] = pk2(v.z, v.w);
    }

    const int* ik = in_idx  + (size_t)k * N_PAIRS;
    const int* ok = out_idx + (size_t)k * N_PAIRS;

    const int warp_global = blockIdx.x * (blockDim.x >> 5) + warp;
    const int stride      = gridDim.x * (blockDim.x >> 5);
    const int base_i      = hi << 4;

    for (int p = warp_global; p < N_PAIRS; p += stride) {
        const int in = ik[p];
        const int ou = ok[p];
        const float f = feats[(size_t)in * C_IN + lane];  // lane l holds input ch l

        unsigned long long a0 = 0ull, a1 = 0ull;   // {0.f,0.f} packed
        #pragma unroll
        for (int j = 0; j < 16; ++j) {
            float fi = __shfl_sync(0xffffffffu, f, base_i + j);
            unsigned long long f2 = pk2(fi, fi);
            a0 = fma2(f2, w0[j], a0);
            a1 = fma2(f2, w1[j], a1);
        }
        float r0, r1, r2, r3;
        unpk2(a0, r0, r1);
        unpk2(a1, r2, r3);
        // combine the two i-halves (partner lane = lane ^ 16, same channels)
        r0 += __shfl_xor_sync(0xffffffffu, r0, 16);
        r1 += __shfl_xor_sync(0xffffffffu, r1, 16);
        r2 += __shfl_xor_sync(0xffffffffu, r2, 16);
        r3 += __shfl_xor_sync(0xffffffffu, r3, 16);

        if (hi == 0) {
            float* dst = out + (size_t)ou * C_OUT + c0;   // 16B-aligned
            asm volatile("red.global.add.v4.f32 [%0], {%1, %2, %3, %4};"
                         :: "l"(dst), "f"(r0), "f"(r1), "f"(r2), "f"(r3)
                         : "memory");
        }
    }
}

// ---------------- K2: per-group sum / sumsq over all points --------------
__global__ void stats_kernel(const float* __restrict__ out) {
    float s[GROUPS], ss[GROUPS];
    #pragma unroll
    for (int g = 0; g < GROUPS; ++g) { s[g] = 0.f; ss[g] = 0.f; }

    const int tid = blockIdx.x * blockDim.x + threadIdx.x;
    const int nth = gridDim.x * blockDim.x;
    for (int r = tid; r < N_POINTS; r += nth) {
        const float4* row = (const float4*)(out + (size_t)r * C_OUT);
        #pragma unroll
        for (int g = 0; g < GROUPS; ++g) {
            float4 a = row[2 * g];
            float4 b = row[2 * g + 1];
            s[g]  += ((a.x + a.y) + (a.z + a.w)) + ((b.x + b.y) + (b.z + b.w));
            ss[g] += ((a.x * a.x + a.y * a.y) + (a.z * a.z + a.w * a.w)) +
                     ((b.x * b.x + b.y * b.y) + (b.z * b.z + b.w * b.w));
        }
    }
    #pragma unroll
    for (int g = 0; g < GROUPS; ++g) {
        #pragma unroll
        for (int off = 16; off > 0; off >>= 1) {
            s[g]  += __shfl_xor_sync(0xffffffffu, s[g],  off);
            ss[g] += __shfl_xor_sync(0xffffffffu, ss[g], off);
        }
    }
    if ((threadIdx.x & 31) == 0) {
        #pragma unroll
        for (int g = 0; g < GROUPS; ++g) {
            atomicAdd(&g_sum[g], s[g]);
            atomicAdd(&g_sqs[g], ss[g]);
        }
    }
}

// ---------------- K3: fold mean/var/gamma/beta into per-channel affine ---
__global__ void params_kernel(const float* __restrict__ gamma,
                              const float* __restrict__ beta) {
    int c = threadIdx.x;
    if (c < C_OUT) {
        int g = c >> 3;  // 8 channels per group
        const float n = (float)N_POINTS * (float)(C_OUT / GROUPS);
        float mean = g_sum[g] / n;
        float var  = g_sqs[g] / n - mean * mean;
        float rs   = rsqrtf(var + EPS_GN);
        float sc   = gamma[c] * rs;
        g_scale[c] = sc;
        g_bias[c]  = beta[c] - mean * sc;
    }
}

// ---------------- K4: normalize + LeakyReLU (in place) -------------------
__global__ void norm_kernel(float4* __restrict__ out) {
    const int total4 = N_POINTS * C_OUT / 4;
    int i = blockIdx.x * blockDim.x + threadIdx.x;
    if (i >= total4) return;
    int q = i & 15;  // which float4 within the 64-channel row
    float4 sc = ((const float4*)g_scale)[q];
    float4 bs = ((const float4*)g_bias)[q];
    float4 v = out[i];
    v.x = v.x * sc.x + bs.x; v.x = (v.x >= 0.f) ? v.x : NEG_SLOPE * v.x;
    v.y = v.y * sc.y + bs.y; v.y = (v.y >= 0.f) ? v.y : NEG_SLOPE * v.y;
    v.z = v.z * sc.z + bs.z; v.z = (v.z >= 0.f) ? v.z : NEG_SLOPE * v.z;
    v.w = v.w * sc.w + bs.w; v.w = (v.w >= 0.f) ? v.w : NEG_SLOPE * v.w;
    out[i] = v;
}

// ---------------- launch ---------------------------------------------------
extern "C" void kernel_launch(void* const* d_in, const int* in_sizes, int n_in,
                              void* d_out, int out_size) {
    const float* feats   = (const float*)d_in[0];   // [N, 32]
    const float* weight  = (const float*)d_in[1];   // [27, 32, 64]
    const float* gamma   = (const float*)d_in[2];   // [64]
    const float* beta    = (const float*)d_in[3];   // [64]
    const int*   in_idx  = (const int*)d_in[4];     // [27, 100000] int32 (JAX x64 off)
    const int*   out_idx = (const int*)d_in[5];     // [27, 100000] int32
    float* out = (float*)d_out;                     // [N, 64]

    const int total4 = N_POINTS * C_OUT / 4;
    const int zblocks = (total4 + 255) / 256;

    zero_kernel<<<zblocks, 256>>>((float4*)out);

    dim3 cgrid(24, K_OFFSETS);                 // 192 warps per kernel offset
    conv_kernel<<<cgrid, 256>>>(feats, weight, in_idx, out_idx, out);

    stats_kernel<<<296, 256>>>(out);
    params_kernel<<<1, 64>>>(gamma, beta);
    norm_kernel<<<zblocks, 256>>>((float4*)out);
}

// round 6
// speedup vs baseline: 2.4135x; 2.4135x over previous
#include <cuda_runtime.h>

#define N_POINTS 300000
#define N_PAIRS  100000
#define K_OFFSETS 27
#define C_IN 32
#define C_OUT 64
#define GROUPS 8
#define EPS_GN 1e-5f
#define NEG_SLOPE 0.01f

typedef unsigned long long ull;

// ---------------- device scratch (no allocations allowed) ----------------
__device__ float g_sum[GROUPS];
__device__ float g_sqs[GROUPS];
__device__ __align__(16) float g_scale[C_OUT];
__device__ __align__(16) float g_bias[C_OUT];

// ---------------- f32x2 packed-math helpers (Blackwell FFMA2) ------------
__device__ __forceinline__ ull pk2(float lo, float hi) {
    ull r;
    asm("mov.b64 %0, {%1, %2};" : "=l"(r) : "f"(lo), "f"(hi));
    return r;
}
__device__ __forceinline__ void unpk2(ull v, float& lo, float& hi) {
    asm("mov.b64 {%0, %1}, %2;" : "=f"(lo), "=f"(hi) : "l"(v));
}
__device__ __forceinline__ ull fma2(ull a, ull b, ull c) {
    ull d;
    asm("fma.rn.f32x2 %0, %1, %2, %3;" : "=l"(d) : "l"(a), "l"(b), "l"(c));
    return d;
}

// ---------------- K0: zero output + zero stat scratch --------------------
__global__ void zero_kernel(float4* __restrict__ out) {
    const int total4 = N_POINTS * C_OUT / 4;
    int i = blockIdx.x * blockDim.x + threadIdx.x;
    if (i < total4) out[i] = make_float4(0.f, 0.f, 0.f, 0.f);
    if (blockIdx.x == 0 && threadIdx.x < GROUPS) {
        g_sum[threadIdx.x] = 0.f;
        g_sqs[threadIdx.x] = 0.f;
    }
}

// ---------------- K1: gather -> 32x64 matmul -> vector scatter-add -------
// One warp per pair, TWO pairs in flight per iteration, with next-iteration
// index+feature loads issued BEFORE the red (memory clobber) so they overlap
// the compute of the current two pairs.
// Lane = hi*16 + q:
//   hi in {0,1}  -> which half of the 32 input channels this lane reduces
//   q  in 0..15  -> this lane owns output channels [4q, 4q+4)
__global__ void __launch_bounds__(256, 2)
conv_kernel(const float* __restrict__ feats,
            const float* __restrict__ weight,
            const int* __restrict__ in_idx,
            const int* __restrict__ out_idx,
            float* __restrict__ out) {
    const int k    = blockIdx.y;
    const int lane = threadIdx.x & 31;
    const int warp = threadIdx.x >> 5;
    const int hi   = lane >> 4;
    const int q    = lane & 15;
    const int c0   = q << 2;

    // Weight slice for this lane: i = hi*16 + j, channels c0..c0+3
    ull w0[16], w1[16];
    const float* wk = weight + (size_t)k * (C_IN * C_OUT);
    #pragma unroll
    for (int j = 0; j < 16; ++j) {
        float4 v = *(const float4*)(wk + (size_t)(hi * 16 + j) * C_OUT + c0);
        w0[j] = pk2(v.x, v.y);
        w1[j] = pk2(v.z, v.w);
    }

    const int* ik = in_idx  + (size_t)k * N_PAIRS;
    const int* ok = out_idx + (size_t)k * N_PAIRS;

    const int stride = gridDim.x * (blockDim.x >> 5);   // warps per k-offset
    const int base_i = hi << 4;

    int p0 = blockIdx.x * (blockDim.x >> 5) + warp;
    int p1 = p0 + stride;
    bool v0 = p0 < N_PAIRS;
    bool v1 = p1 < N_PAIRS;

    int ou0 = 0, ou1 = 0;
    float f0 = 0.f, f1 = 0.f;
    if (v0) { int in0 = ik[p0]; ou0 = ok[p0]; f0 = feats[(size_t)in0 * C_IN + lane]; }
    if (v1) { int in1 = ik[p1]; ou1 = ok[p1]; f1 = feats[(size_t)in1 * C_IN + lane]; }

    while (v0) {
        // ---- prefetch next two pairs (in flight during compute below) ----
        const int np0 = p0 + 2 * stride;
        const int np1 = p1 + 2 * stride;
        const bool nv0 = np0 < N_PAIRS;
        const bool nv1 = np1 < N_PAIRS;
        int nou0 = 0, nou1 = 0;
        float nf0 = 0.f, nf1 = 0.f;
        if (nv0) { int nin0 = ik[np0]; nou0 = ok[np0]; nf0 = feats[(size_t)nin0 * C_IN + lane]; }
        if (nv1) { int nin1 = ik[np1]; nou1 = ok[np1]; nf1 = feats[(size_t)nin1 * C_IN + lane]; }

        // ---- compute both pairs, interleaved for ILP ----
        ull a0 = 0ull, a1 = 0ull;   // pair 0, channels {c0,c0+1} / {c0+2,c0+3}
        ull b0 = 0ull, b1 = 0ull;   // pair 1
        #pragma unroll
        for (int j = 0; j < 16; ++j) {
            float fa = __shfl_sync(0xffffffffu, f0, base_i + j);
            float fb = __shfl_sync(0xffffffffu, f1, base_i + j);
            ull fa2 = pk2(fa, fa);
            ull fb2 = pk2(fb, fb);
            a0 = fma2(fa2, w0[j], a0);
            b0 = fma2(fb2, w0[j], b0);
            a1 = fma2(fa2, w1[j], a1);
            b1 = fma2(fb2, w1[j], b1);
        }

        float r0, r1, r2, r3, s0, s1, s2, s3;
        unpk2(a0, r0, r1); unpk2(a1, r2, r3);
        unpk2(b0, s0, s1); unpk2(b1, s2, s3);
        // combine the two i-halves (partner lane = lane ^ 16, same channels)
        r0 += __shfl_xor_sync(0xffffffffu, r0, 16);
        r1 += __shfl_xor_sync(0xffffffffu, r1, 16);
        r2 += __shfl_xor_sync(0xffffffffu, r2, 16);
        r3 += __shfl_xor_sync(0xffffffffu, r3, 16);
        s0 += __shfl_xor_sync(0xffffffffu, s0, 16);
        s1 += __shfl_xor_sync(0xffffffffu, s1, 16);
        s2 += __shfl_xor_sync(0xffffffffu, s2, 16);
        s3 += __shfl_xor_sync(0xffffffffu, s3, 16);

        if (hi == 0) {
            float* dst0 = out + (size_t)ou0 * C_OUT + c0;   // 16B-aligned
            asm volatile("red.global.add.v4.f32 [%0], {%1, %2, %3, %4};"
                         :: "l"(dst0), "f"(r0), "f"(r1), "f"(r2), "f"(r3)
                         : "memory");
        }
        if (v1 && hi == 0) {
            float* dst1 = out + (size_t)ou1 * C_OUT + c0;
            asm volatile("red.global.add.v4.f32 [%0], {%1, %2, %3, %4};"
                         :: "l"(dst1), "f"(s0), "f"(s1), "f"(s2), "f"(s3)
                         : "memory");
        }

        // ---- rotate pipeline ----
        p0 = np0; p1 = np1; v0 = nv0; v1 = nv1;
        ou0 = nou0; ou1 = nou1; f0 = nf0; f1 = nf1;
    }
}

// ---------------- K2: per-group sum / sumsq over all points --------------
__global__ void stats_kernel(const float* __restrict__ out) {
    float s[GROUPS], ss[GROUPS];
    #pragma unroll
    for (int g = 0; g < GROUPS; ++g) { s[g] = 0.f; ss[g] = 0.f; }

    const int tid = blockIdx.x * blockDim.x + threadIdx.x;
    const int nth = gridDim.x * blockDim.x;
    for (int r = tid; r < N_POINTS; r += nth) {
        const float4* row = (const float4*)(out + (size_t)r * C_OUT);
        #pragma unroll
        for (int g = 0; g < GROUPS; ++g) {
            float4 a = row[2 * g];
            float4 b = row[2 * g + 1];
            s[g]  += ((a.x + a.y) + (a.z + a.w)) + ((b.x + b.y) + (b.z + b.w));
            ss[g] += ((a.x * a.x + a.y * a.y) + (a.z * a.z + a.w * a.w)) +
                     ((b.x * b.x + b.y * b.y) + (b.z * b.z + b.w * b.w));
        }
    }
    #pragma unroll
    for (int g = 0; g < GROUPS; ++g) {
        #pragma unroll
        for (int off = 16; off > 0; off >>= 1) {
            s[g]  += __shfl_xor_sync(0xffffffffu, s[g],  off);
            ss[g] += __shfl_xor_sync(0xffffffffu, ss[g], off);
        }
    }
    if ((threadIdx.x & 31) == 0) {
        #pragma unroll
        for (int g = 0; g < GROUPS; ++g) {
            atomicAdd(&g_sum[g], s[g]);
            atomicAdd(&g_sqs[g], ss[g]);
        }
    }
}

// ---------------- K3: fold mean/var/gamma/beta into per-channel affine ---
__global__ void params_kernel(const float* __restrict__ gamma,
                              const float* __restrict__ beta) {
    int c = threadIdx.x;
    if (c < C_OUT) {
        int g = c >> 3;  // 8 channels per group
        const float n = (float)N_POINTS * (float)(C_OUT / GROUPS);
        float mean = g_sum[g] / n;
        float var  = g_sqs[g] / n - mean * mean;
        float rs   = rsqrtf(var + EPS_GN);
        float sc   = gamma[c] * rs;
        g_scale[c] = sc;
        g_bias[c]  = beta[c] - mean * sc;
    }
}

// ---------------- K4: normalize + LeakyReLU (in place) -------------------
__global__ void norm_kernel(float4* __restrict__ out) {
    const int total4 = N_POINTS * C_OUT / 4;
    int i = blockIdx.x * blockDim.x + threadIdx.x;
    if (i >= total4) return;
    int q = i & 15;  // which float4 within the 64-channel row
    float4 sc = ((const float4*)g_scale)[q];
    float4 bs = ((const float4*)g_bias)[q];
    float4 v = out[i];
    v.x = v.x * sc.x + bs.x; v.x = (v.x >= 0.f) ? v.x : NEG_SLOPE * v.x;
    v.y = v.y * sc.y + bs.y; v.y = (v.y >= 0.f) ? v.y : NEG_SLOPE * v.y;
    v.z = v.z * sc.z + bs.z; v.z = (v.z >= 0.f) ? v.z : NEG_SLOPE * v.z;
    v.w = v.w * sc.w + bs.w; v.w = (v.w >= 0.f) ? v.w : NEG_SLOPE * v.w;
    out[i] = v;
}

// ---------------- launch ---------------------------------------------------
extern "C" void kernel_launch(void* const* d_in, const int* in_sizes, int n_in,
                              void* d_out, int out_size) {
    const float* feats   = (const float*)d_in[0];   // [N, 32]
    const float* weight  = (const float*)d_in[1];   // [27, 32, 64]
    const float* gamma   = (const float*)d_in[2];   // [64]
    const float* beta    = (const float*)d_in[3];   // [64]
    const int*   in_idx  = (const int*)d_in[4];     // [27, 100000] int32
    const int*   out_idx = (const int*)d_in[5];     // [27, 100000] int32
    float* out = (float*)d_out;                     // [N, 64]

    const int total4 = N_POINTS * C_OUT / 4;
    const int zblocks = (total4 + 255) / 256;

    zero_kernel<<<zblocks, 256>>>((float4*)out);

    dim3 cgrid(24, K_OFFSETS);                 // 192 warps per kernel offset
    conv_kernel<<<cgrid, 256>>>(feats, weight, in_idx, out_idx, out);

    stats_kernel<<<296, 256>>>(out);
    params_kernel<<<1, 64>>>(gamma, beta);
    norm_kernel<<<zblocks, 256>>>((float4*)out);
}

// round 7
// speedup vs baseline: 3.7003x; 1.5332x over previous
#include <cuda_runtime.h>

#define N_POINTS 300000
#define N_PAIRS  100000
#define K_OFFSETS 27
#define C_IN 32
#define C_OUT 64
#define GROUPS 8
#define EPS_GN 1e-5f
#define NEG_SLOPE 0.01f

typedef unsigned long long ull;

// ---------------- device scratch (no allocations allowed) ----------------
__device__ float g_sum[GROUPS];
__device__ float g_sqs[GROUPS];
__device__ __align__(16) float g_scale[C_OUT];
__device__ __align__(16) float g_bias[C_OUT];

// ---------------- f32x2 packed-math helpers (Blackwell FFMA2) ------------
__device__ __forceinline__ ull pk2(float lo, float hi) {
    ull r;
    asm("mov.b64 %0, {%1, %2};" : "=l"(r) : "f"(lo), "f"(hi));
    return r;
}
__device__ __forceinline__ void unpk2(ull v, float& lo, float& hi) {
    asm("mov.b64 {%0, %1}, %2;" : "=f"(lo), "=f"(hi) : "l"(v));
}
__device__ __forceinline__ ull fma2(ull a, ull b, ull c) {
    ull d;
    asm("fma.rn.f32x2 %0, %1, %2, %3;" : "=l"(d) : "l"(a), "l"(b), "l"(c));
    return d;
}

// ---------------- K0: zero output + zero stat scratch --------------------
__global__ void zero_kernel(float4* __restrict__ out) {
    const int total4 = N_POINTS * C_OUT / 4;
    int i = blockIdx.x * blockDim.x + threadIdx.x;
    if (i < total4) out[i] = make_float4(0.f, 0.f, 0.f, 0.f);
    if (blockIdx.x == 0 && threadIdx.x < GROUPS) {
        g_sum[threadIdx.x] = 0.f;
        g_sqs[threadIdx.x] = 0.f;
    }
}

// ---------------- K1: gather -> 32x64 matmul -> vector scatter-add -------
// One warp, two pairs per pipeline stage. THREE-stage software pipeline:
//   stage C: indices loaded this iteration            (ik/ok -> regs)
//   stage B: feats gather issued this iteration using indices loaded last iter
//   stage A: compute + scatter using feats issued last iteration
// This fully decouples the serial ik -> feats dependency: each load class
// has a whole iteration (~compute latency) in flight before its consumer.
// Lane = hi*16 + q: hi = which half of C_IN this lane reduces,
//                   q  = owns output channels [4q, 4q+4).
__global__ void __launch_bounds__(256, 2)
conv_kernel(const float* __restrict__ feats,
            const float* __restrict__ weight,
            const int* __restrict__ in_idx,
            const int* __restrict__ out_idx,
            float* __restrict__ out) {
    const int k    = blockIdx.y;
    const int lane = threadIdx.x & 31;
    const int warp = threadIdx.x >> 5;
    const int hi   = lane >> 4;
    const int q    = lane & 15;
    const int c0   = q << 2;

    // Weight slice for this lane: i = hi*16 + j, channels c0..c0+3
    ull w0[16], w1[16];
    const float* wk = weight + (size_t)k * (C_IN * C_OUT);
    #pragma unroll
    for (int j = 0; j < 16; ++j) {
        float4 v = *(const float4*)(wk + (size_t)(hi * 16 + j) * C_OUT + c0);
        w0[j] = pk2(v.x, v.y);
        w1[j] = pk2(v.z, v.w);
    }

    const int* ik = in_idx  + (size_t)k * N_PAIRS;
    const int* ok = out_idx + (size_t)k * N_PAIRS;

    const int s      = gridDim.x * (blockDim.x >> 5);   // warps per k-offset
    const int base_i = hi << 4;
    const int pstart = blockIdx.x * (blockDim.x >> 5) + warp;

    // ---- prologue ----
    // Stage A (computed first): indices AND feats loaded serially once.
    int  pA  = pstart;
    bool vA0 = pA < N_PAIRS, vA1 = pA + s < N_PAIRS;
    int  oA0 = 0, oA1 = 0;
    float fA0 = 0.f, fA1 = 0.f;
    if (vA0) { int i0 = ik[pA];     oA0 = ok[pA];     fA0 = feats[(size_t)i0 * C_IN + lane]; }
    if (vA1) { int i1 = ik[pA + s]; oA1 = ok[pA + s]; fA1 = feats[(size_t)i1 * C_IN + lane]; }
    // Stage B: indices resident, feats issued at first loop top.
    int  pB  = pA + 2 * s;
    bool vB0 = pB < N_PAIRS, vB1 = pB + s < N_PAIRS;
    int  iB0 = 0, iB1 = 0, oB0 = 0, oB1 = 0;
    if (vB0) { iB0 = ik[pB];     oB0 = ok[pB]; }
    if (vB1) { iB1 = ik[pB + s]; oB1 = ok[pB + s]; }
    // Stage C: index pointer only.
    int pC = pB + 2 * s;

    while (vA0) {
        // -- issue feats for stage B (indices already resident) --
        float fB0 = 0.f, fB1 = 0.f;
        if (vB0) fB0 = feats[(size_t)iB0 * C_IN + lane];
        if (vB1) fB1 = feats[(size_t)iB1 * C_IN + lane];

        // -- load indices for stage C --
        const bool vC0 = pC < N_PAIRS, vC1 = pC + s < N_PAIRS;
        int iC0 = 0, iC1 = 0, oC0 = 0, oC1 = 0;
        if (vC0) { iC0 = ik[pC];     oC0 = ok[pC]; }
        if (vC1) { iC1 = ik[pC + s]; oC1 = ok[pC + s]; }

        // -- compute stage A: two pairs, interleaved for ILP --
        ull a0 = 0ull, a1 = 0ull;   // pair 0, channels {c0,c0+1} / {c0+2,c0+3}
        ull b0 = 0ull, b1 = 0ull;   // pair 1
        #pragma unroll
        for (int j = 0; j < 16; ++j) {
            float fa = __shfl_sync(0xffffffffu, fA0, base_i + j);
            float fb = __shfl_sync(0xffffffffu, fA1, base_i + j);
            ull fa2 = pk2(fa, fa);
            ull fb2 = pk2(fb, fb);
            a0 = fma2(fa2, w0[j], a0);
            b0 = fma2(fb2, w0[j], b0);
            a1 = fma2(fa2, w1[j], a1);
            b1 = fma2(fb2, w1[j], b1);
        }

        float r0, r1, r2, r3, s0, s1, s2, s3;
        unpk2(a0, r0, r1); unpk2(a1, r2, r3);
        unpk2(b0, s0, s1); unpk2(b1, s2, s3);
        // combine the two i-halves (partner lane = lane ^ 16, same channels)
        r0 += __shfl_xor_sync(0xffffffffu, r0, 16);
        r1 += __shfl_xor_sync(0xffffffffu, r1, 16);
        r2 += __shfl_xor_sync(0xffffffffu, r2, 16);
        r3 += __shfl_xor_sync(0xffffffffu, r3, 16);
        s0 += __shfl_xor_sync(0xffffffffu, s0, 16);
        s1 += __shfl_xor_sync(0xffffffffu, s1, 16);
        s2 += __shfl_xor_sync(0xffffffffu, s2, 16);
        s3 += __shfl_xor_sync(0xffffffffu, s3, 16);

        if (hi == 0) {
            float* dst0 = out + (size_t)oA0 * C_OUT + c0;   // 16B-aligned
            asm volatile("red.global.add.v4.f32 [%0], {%1, %2, %3, %4};"
                         :: "l"(dst0), "f"(r0), "f"(r1), "f"(r2), "f"(r3)
                         : "memory");
            if (vA1) {
                float* dst1 = out + (size_t)oA1 * C_OUT + c0;
                asm volatile("red.global.add.v4.f32 [%0], {%1, %2, %3, %4};"
                             :: "l"(dst1), "f"(s0), "f"(s1), "f"(s2), "f"(s3)
                             : "memory");
            }
        }

        // -- rotate pipeline: A <- B (feats in flight), B <- C (indices) --
        fA0 = fB0; fA1 = fB1; oA0 = oB0; oA1 = oB1; vA0 = vB0; vA1 = vB1;
        iB0 = iC0; iB1 = iC1; oB0 = oC0; oB1 = oC1; vB0 = vC0; vB1 = vC1;
        pC += 2 * s;
    }
}

// ---------------- K2: per-group sum / sumsq over all points --------------
__global__ void stats_kernel(const float* __restrict__ out) {
    float s[GROUPS], ss[GROUPS];
    #pragma unroll
    for (int g = 0; g < GROUPS; ++g) { s[g] = 0.f; ss[g] = 0.f; }

    const int tid = blockIdx.x * blockDim.x + threadIdx.x;
    const int nth = gridDim.x * blockDim.x;
    for (int r = tid; r < N_POINTS; r += nth) {
        const float4* row = (const float4*)(out + (size_t)r * C_OUT);
        #pragma unroll
        for (int g = 0; g < GROUPS; ++g) {
            float4 a = row[2 * g];
            float4 b = row[2 * g + 1];
            s[g]  += ((a.x + a.y) + (a.z + a.w)) + ((b.x + b.y) + (b.z + b.w));
            ss[g] += ((a.x * a.x + a.y * a.y) + (a.z * a.z + a.w * a.w)) +
                     ((b.x * b.x + b.y * b.y) + (b.z * b.z + b.w * b.w));
        }
    }
    #pragma unroll
    for (int g = 0; g < GROUPS; ++g) {
        #pragma unroll
        for (int off = 16; off > 0; off >>= 1) {
            s[g]  += __shfl_xor_sync(0xffffffffu, s[g],  off);
            ss[g] += __shfl_xor_sync(0xffffffffu, ss[g], off);
        }
    }
    if ((threadIdx.x & 31) == 0) {
        #pragma unroll
        for (int g = 0; g < GROUPS; ++g) {
            atomicAdd(&g_sum[g], s[g]);
            atomicAdd(&g_sqs[g], ss[g]);
        }
    }
}

// ---------------- K3: fold mean/var/gamma/beta into per-channel affine ---
__global__ void params_kernel(const float* __restrict__ gamma,
                              const float* __restrict__ beta) {
    int c = threadIdx.x;
    if (c < C_OUT) {
        int g = c >> 3;  // 8 channels per group
        const float n = (float)N_POINTS * (float)(C_OUT / GROUPS);
        float mean = g_sum[g] / n;
        float var  = g_sqs[g] / n - mean * mean;
        float rs   = rsqrtf(var + EPS_GN);
        float sc   = gamma[c] * rs;
        g_scale[c] = sc;
        g_bias[c]  = beta[c] - mean * sc;
    }
}

// ---------------- K4: normalize + LeakyReLU (in place) -------------------
__global__ void norm_kernel(float4* __restrict__ out) {
    const int total4 = N_POINTS * C_OUT / 4;
    int i = blockIdx.x * blockDim.x + threadIdx.x;
    if (i >= total4) return;
    int q = i & 15;  // which float4 within the 64-channel row
    float4 sc = ((const float4*)g_scale)[q];
    float4 bs = ((const float4*)g_bias)[q];
    float4 v = out[i];
    v.x = v.x * sc.x + bs.x; v.x = (v.x >= 0.f) ? v.x : NEG_SLOPE * v.x;
    v.y = v.y * sc.y + bs.y; v.y = (v.y >= 0.f) ? v.y : NEG_SLOPE * v.y;
    v.z = v.z * sc.z + bs.z; v.z = (v.z >= 0.f) ? v.z : NEG_SLOPE * v.z;
    v.w = v.w * sc.w + bs.w; v.w = (v.w >= 0.f) ? v.w : NEG_SLOPE * v.w;
    out[i] = v;
}

// ---------------- launch ---------------------------------------------------
extern "C" void kernel_launch(void* const* d_in, const int* in_sizes, int n_in,
                              void* d_out, int out_size) {
    const float* feats   = (const float*)d_in[0];   // [N, 32]
    const float* weight  = (const float*)d_in[1];   // [27, 32, 64]
    const float* gamma   = (const float*)d_in[2];   // [64]
    const float* beta    = (const float*)d_in[3];   // [64]
    const int*   in_idx  = (const int*)d_in[4];     // [27, 100000] int32
    const int*   out_idx = (const int*)d_in[5];     // [27, 100000] int32
    float* out = (float*)d_out;                     // [N, 64]

    const int total4 = N_POINTS * C_OUT / 4;
    const int zblocks = (total4 + 255) / 256;

    zero_kernel<<<zblocks, 256>>>((float4*)out);

    // 21 x 27 = 567 CTAs <= 592 resident (148 SMs x occ 2) -> exactly 2 waves,
    // no partial third wave (R6 used 648 = 2 waves + 56-CTA tail).
    dim3 cgrid(21, K_OFFSETS);
    conv_kernel<<<cgrid, 256>>>(feats, weight, in_idx, out_idx, out);

    stats_kernel<<<296, 256>>>(out);
    params_kernel<<<1, 64>>>(gamma, beta);
    norm_kernel<<<zblocks, 256>>>((float4*)out);
}

// round 8
// speedup vs baseline: 3.9642x; 1.0713x over previous
#include <cuda_runtime.h>

#define N_POINTS 300000
#define N_PAIRS  100000
#define K_OFFSETS 27
#define C_IN 32
#define C_OUT 64
#define GROUPS 8
#define EPS_GN 1e-5f
#define NEG_SLOPE 0.01f

typedef unsigned long long ull;

// ---------------- device scratch (no allocations allowed) ----------------
__device__ float g_sum[GROUPS];
__device__ float g_sqs[GROUPS];
__device__ unsigned g_done;
__device__ __align__(16) float g_scale[C_OUT];
__device__ __align__(16) float g_bias[C_OUT];

// ---------------- f32x2 packed-math helpers (Blackwell) ------------------
__device__ __forceinline__ ull pk2(float lo, float hi) {
    ull r;
    asm("mov.b64 %0, {%1, %2};" : "=l"(r) : "f"(lo), "f"(hi));
    return r;
}
__device__ __forceinline__ void unpk2(ull v, float& lo, float& hi) {
    asm("mov.b64 {%0, %1}, %2;" : "=f"(lo), "=f"(hi) : "l"(v));
}
__device__ __forceinline__ ull fma2(ull a, ull b, ull c) {
    ull d;
    asm("fma.rn.f32x2 %0, %1, %2, %3;" : "=l"(d) : "l"(a), "l"(b), "l"(c));
    return d;
}
__device__ __forceinline__ ull add2(ull a, ull b) {
    ull d;
    asm("add.rn.f32x2 %0, %1, %2;" : "=l"(d) : "l"(a), "l"(b));
    return d;
}
// combine lane with partner (lane ^ 16) on a packed accumulator
__device__ __forceinline__ ull halfcomb(ull v) {
    return add2(v, __shfl_xor_sync(0xffffffffu, v, 16));
}
__device__ __forceinline__ void red4(float* dst, ull lo, ull hi) {
    float r0, r1, r2, r3;
    unpk2(lo, r0, r1);
    unpk2(hi, r2, r3);
    asm volatile("red.global.add.v4.f32 [%0], {%1, %2, %3, %4};"
                 :: "l"(dst), "f"(r0), "f"(r1), "f"(r2), "f"(r3) : "memory");
}

// ---------------- K0: zero output + zero scratch -------------------------
__global__ void zero_kernel(float4* __restrict__ out) {
    const int total4 = N_POINTS * C_OUT / 4;
    int i = blockIdx.x * blockDim.x + threadIdx.x;
    if (i < total4) out[i] = make_float4(0.f, 0.f, 0.f, 0.f);
    if (blockIdx.x == 0 && threadIdx.x < GROUPS) {
        g_sum[threadIdx.x] = 0.f;
        g_sqs[threadIdx.x] = 0.f;
        if (threadIdx.x == 0) g_done = 0u;
    }
}

// ---------------- K1: gather -> 32x64 matmul -> vector scatter-add -------
// One warp processes contiguous QUADS of 4 pairs (int4 index loads;
// 100000 % 4 == 0 so every in-range quad is full). Three-stage pipeline:
//   C: int4 index loads        B: feats gathers (idx from last iter)
//   A: compute + scatter       (feats from last iter)
// Lane = hi*16 + q: hi = which half of C_IN this lane reduces,
//                   q  = owns output channels [4q, 4q+4).
__global__ void __launch_bounds__(256, 2)
conv_kernel(const float* __restrict__ feats,
            const float* __restrict__ weight,
            const int* __restrict__ in_idx,
            const int* __restrict__ out_idx,
            float* __restrict__ out) {
    const int k    = blockIdx.y;
    const int lane = threadIdx.x & 31;
    const int warp = threadIdx.x >> 5;
    const int hi   = lane >> 4;
    const int q    = lane & 15;
    const int c0   = q << 2;

    // Weight slice for this lane: i = hi*16 + j, channels c0..c0+3
    ull w0[16], w1[16];
    const float* wk = weight + (size_t)k * (C_IN * C_OUT);
    #pragma unroll
    for (int j = 0; j < 16; ++j) {
        float4 v = *(const float4*)(wk + (size_t)(hi * 16 + j) * C_OUT + c0);
        w0[j] = pk2(v.x, v.y);
        w1[j] = pk2(v.z, v.w);
    }

    const int* ik = in_idx  + (size_t)k * N_PAIRS;
    const int* ok = out_idx + (size_t)k * N_PAIRS;

    const int base_i  = hi << 4;
    const int wg      = blockIdx.x * (blockDim.x >> 5) + warp;
    const int qstride = (gridDim.x * (blockDim.x >> 5)) << 2; // pairs/sweep

    // ---- prologue ----
    int bA = wg << 2;
    bool vA = bA < N_PAIRS;
    int4 oA = make_int4(0, 0, 0, 0);
    float fA0 = 0.f, fA1 = 0.f, fA2 = 0.f, fA3 = 0.f;
    if (vA) {
        int4 ia = *(const int4*)(ik + bA);
        oA      = *(const int4*)(ok + bA);
        fA0 = feats[(size_t)ia.x * C_IN + lane];
        fA1 = feats[(size_t)ia.y * C_IN + lane];
        fA2 = feats[(size_t)ia.z * C_IN + lane];
        fA3 = feats[(size_t)ia.w * C_IN + lane];
    }
    int bB = bA + qstride;
    bool vB = bB < N_PAIRS;
    int4 iB = make_int4(0, 0, 0, 0), oB = make_int4(0, 0, 0, 0);
    if (vB) { iB = *(const int4*)(ik + bB); oB = *(const int4*)(ok + bB); }
    int bC = bB + qstride;

    while (vA) {
        // -- stage B: issue feats gathers (indices already resident) --
        float fB0 = 0.f, fB1 = 0.f, fB2 = 0.f, fB3 = 0.f;
        if (vB) {
            fB0 = feats[(size_t)iB.x * C_IN + lane];
            fB1 = feats[(size_t)iB.y * C_IN + lane];
            fB2 = feats[(size_t)iB.z * C_IN + lane];
            fB3 = feats[(size_t)iB.w * C_IN + lane];
        }
        // -- stage C: load next indices --
        const bool vC = bC < N_PAIRS;
        int4 iC = make_int4(0, 0, 0, 0), oC = make_int4(0, 0, 0, 0);
        if (vC) { iC = *(const int4*)(ik + bC); oC = *(const int4*)(ok + bC); }

        // -- stage A: compute 4 pairs, 8 independent FMA2 chains --
        ull a00 = 0ull, a01 = 0ull, a10 = 0ull, a11 = 0ull;
        ull a20 = 0ull, a21 = 0ull, a30 = 0ull, a31 = 0ull;
        #pragma unroll
        for (int j = 0; j < 16; ++j) {
            const int src = base_i + j;
            float g0 = __shfl_sync(0xffffffffu, fA0, src);
            float g1 = __shfl_sync(0xffffffffu, fA1, src);
            float g2 = __shfl_sync(0xffffffffu, fA2, src);
            float g3 = __shfl_sync(0xffffffffu, fA3, src);
            ull p0 = pk2(g0, g0);
            ull p1 = pk2(g1, g1);
            ull p2 = pk2(g2, g2);
            ull p3 = pk2(g3, g3);
            a00 = fma2(p0, w0[j], a00);  a01 = fma2(p0, w1[j], a01);
            a10 = fma2(p1, w0[j], a10);  a11 = fma2(p1, w1[j], a11);
            a20 = fma2(p2, w0[j], a20);  a21 = fma2(p2, w1[j], a21);
            a30 = fma2(p3, w0[j], a30);  a31 = fma2(p3, w1[j], a31);
        }

        // packed half-combine (8 parallel chains)
        a00 = halfcomb(a00);  a01 = halfcomb(a01);
        a10 = halfcomb(a10);  a11 = halfcomb(a11);
        a20 = halfcomb(a20);  a21 = halfcomb(a21);
        a30 = halfcomb(a30);  a31 = halfcomb(a31);

        if (hi == 0) {
            red4(out + (size_t)oA.x * C_OUT + c0, a00, a01);
            red4(out + (size_t)oA.y * C_OUT + c0, a10, a11);
            red4(out + (size_t)oA.z * C_OUT + c0, a20, a21);
            red4(out + (size_t)oA.w * C_OUT + c0, a30, a31);
        }

        // -- rotate pipeline --
        fA0 = fB0; fA1 = fB1; fA2 = fB2; fA3 = fB3;
        oA = oB; vA = vB;
        iB = iC; oB = oC; vB = vC;
        bC += qstride;
    }
}

// ---------------- K2: group stats + (last block) fold params -------------
__global__ void stats_kernel(const float* __restrict__ out,
                             const float* __restrict__ gamma,
                             const float* __restrict__ beta) {
    float s[GROUPS], ss[GROUPS];
    #pragma unroll
    for (int g = 0; g < GROUPS; ++g) { s[g] = 0.f; ss[g] = 0.f; }

    const int tid = blockIdx.x * blockDim.x + threadIdx.x;
    const int nth = gridDim.x * blockDim.x;
    for (int r = tid; r < N_POINTS; r += nth) {
        const float4* row = (const float4*)(out + (size_t)r * C_OUT);
        #pragma unroll
        for (int g = 0; g < GROUPS; ++g) {
            float4 a = row[2 * g];
            float4 b = row[2 * g + 1];
            s[g]  += ((a.x + a.y) + (a.z + a.w)) + ((b.x + b.y) + (b.z + b.w));
            ss[g] += ((a.x * a.x + a.y * a.y) + (a.z * a.z + a.w * a.w)) +
                     ((b.x * b.x + b.y * b.y) + (b.z * b.z + b.w * b.w));
        }
    }
    #pragma unroll
    for (int g = 0; g < GROUPS; ++g) {
        #pragma unroll
        for (int off = 16; off > 0; off >>= 1) {
            s[g]  += __shfl_xor_sync(0xffffffffu, s[g],  off);
            ss[g] += __shfl_xor_sync(0xffffffffu, ss[g], off);
        }
    }
    if ((threadIdx.x & 31) == 0) {
        #pragma unroll
        for (int g = 0; g < GROUPS; ++g) {
            atomicAdd(&g_sum[g], s[g]);
            atomicAdd(&g_sqs[g], ss[g]);
        }
    }
    __syncthreads();
    if (threadIdx.x == 0) {
        __threadfence();
        unsigned t = atomicInc(&g_done, 0xffffffffu);
        if (t == gridDim.x - 1) {   // last block folds mean/var/gamma/beta
            const float n = (float)N_POINTS * (float)(C_OUT / GROUPS);
            #pragma unroll
            for (int c = 0; c < C_OUT; ++c) {
                int g = c >> 3;
                float mean = g_sum[g] / n;
                float var  = g_sqs[g] / n - mean * mean;
                float rs   = rsqrtf(var + EPS_GN);
                float sc   = gamma[c] * rs;
                g_scale[c] = sc;
                g_bias[c]  = beta[c] - mean * sc;
            }
        }
    }
}

// ---------------- K3: normalize + LeakyReLU (in place) -------------------
__global__ void norm_kernel(float4* __restrict__ out) {
    const int total4 = N_POINTS * C_OUT / 4;
    int i = blockIdx.x * blockDim.x + threadIdx.x;
    if (i >= total4) return;
    int q = i & 15;  // which float4 within the 64-channel row
    float4 sc = ((const float4*)g_scale)[q];
    float4 bs = ((const float4*)g_bias)[q];
    float4 v = out[i];
    v.x = v.x * sc.x + bs.x; v.x = (v.x >= 0.f) ? v.x : NEG_SLOPE * v.x;
    v.y = v.y * sc.y + bs.y; v.y = (v.y >= 0.f) ? v.y : NEG_SLOPE * v.y;
    v.z = v.z * sc.z + bs.z; v.z = (v.z >= 0.f) ? v.z : NEG_SLOPE * v.z;
    v.w = v.w * sc.w + bs.w; v.w = (v.w >= 0.f) ? v.w : NEG_SLOPE * v.w;
    out[i] = v;
}

// ---------------- launch ---------------------------------------------------
extern "C" void kernel_launch(void* const* d_in, const int* in_sizes, int n_in,
                              void* d_out, int out_size) {
    const float* feats   = (const float*)d_in[0];   // [N, 32]
    const float* weight  = (const float*)d_in[1];   // [27, 32, 64]
    const float* gamma   = (const float*)d_in[2];   // [64]
    const float* beta    = (const float*)d_in[3];   // [64]
    const int*   in_idx  = (const int*)d_in[4];     // [27, 100000] int32
    const int*   out_idx = (const int*)d_in[5];     // [27, 100000] int32
    float* out = (float*)d_out;                     // [N, 64]

    const int total4 = N_POINTS * C_OUT / 4;
    const int zblocks = (total4 + 255) / 256;

    zero_kernel<<<zblocks, 256>>>((float4*)out);

    // 21 x 27 = 567 CTAs <= 592 resident (148 SMs x occ 2) -> exactly 2 waves.
    dim3 cgrid(21, K_OFFSETS);
    conv_kernel<<<cgrid, 256>>>(feats, weight, in_idx, out_idx, out);

    stats_kernel<<<296, 256>>>(out, gamma, beta);
    norm_kernel<<<zblocks, 256>>>((float4*)out);
}